// round 7
// baseline (speedup 1.0000x reference)
#include <cuda_runtime.h>
#include <cstdint>

// Problem constants
#define BATCH 32
#define NEXP 8
#define CIN 64
#define COUT 64
#define HW 25600            // 160*160
#define NTILE 64            // pixels per warpgroup-tile
#define ITERS 8             // tiles per warpgroup
#define XS 72               // smem row stride (72 mod 32 = 8 -> conflict-free)
#define STAGE_F (CIN * XS)  // 4608 floats = 18432 B per stage
#define NBUF 3
#define SMEM_BYTES (2 * NBUF * STAGE_F * 4)   // 110592 B -> 2 CTAs/SM

// Per-batch mixed weight matrices, TF32-rounded, [B][COUT][CIN]
__device__ float g_W[BATCH * COUT * CIN];

__device__ __forceinline__ uint32_t f2tf32(float f) {
    uint32_t r;
    asm("cvt.rna.tf32.f32 %0, %1;" : "=r"(r) : "f"(f));
    return r;
}

__device__ __forceinline__ void cp_async16(float* dst_smem, const float* src_gmem) {
    uint32_t d = (uint32_t)__cvta_generic_to_shared(dst_smem);
    asm volatile("cp.async.cg.shared.global [%0], [%1], 16;\n" :: "r"(d), "l"(src_gmem));
}
__device__ __forceinline__ void cp_commit() {
    asm volatile("cp.async.commit_group;\n" ::: "memory");
}
template<int N>
__device__ __forceinline__ void cp_wait() {
    asm volatile("cp.async.wait_group %0;\n" :: "n"(N) : "memory");
}
__device__ __forceinline__ void wg_bar(int id) {
    asm volatile("bar.sync %0, 128;\n" :: "r"(id) : "memory");
}

// Kernel 1: W_b[o,i] = (1+3.38e-4) * sum_e alpha[b,e] * ke[e,o,i], tf32-RNA.
// Scale cancels first-order truncation bias of raw-fp32 X bits into tf32 MMA.
__global__ void lla_weights_kernel(const float* __restrict__ alpha,
                                   const float* __restrict__ ke) {
    const int b = blockIdx.x;
    __shared__ float a_s[NEXP];
    if (threadIdx.x < NEXP) a_s[threadIdx.x] = alpha[b * NEXP + threadIdx.x];
    __syncthreads();
    const int i0 = blockIdx.y * 1024 + threadIdx.x;
#pragma unroll 4
    for (int i = i0; i < (blockIdx.y + 1) * 1024; i += 256) {
        float s = 0.f;
#pragma unroll
        for (int e = 0; e < NEXP; e++)
            s = fmaf(a_s[e], ke[e * COUT * CIN + i], s);
        g_W[b * COUT * CIN + i] = __uint_as_float(f2tf32(s * 1.000338f));
    }
}

// Kernel 2: per-batch GEMM via tf32 mma.sync.
// CTA = 2 independent warpgroups of 4 warps. Each wg owns a 64px-wide strip
// with a private 3-stage cp.async ring and a named barrier. Within a wg,
// warp (mi,ni) computes M-rows [32mi,32mi+32) x pixels [32ni,32ni+32).
// W fragments live entirely in registers (64 regs); smem X read only 2x.
__global__ __launch_bounds__(256, 2)
void lla_conv_kernel(const float* __restrict__ x, float* __restrict__ out) {
    extern __shared__ float smem[];

    const int b    = blockIdx.y;
    const int tid  = threadIdx.x;
    const int lane = tid & 31;
    const int wg   = tid >> 7;          // warpgroup 0/1
    const int wtid = tid & 127;         // thread id within wg
    const int wig  = (tid >> 5) & 3;    // warp in group
    const int mi   = wig & 1;           // M half
    const int ni   = wig >> 1;          // N half
    const int g    = lane >> 2;         // 0..7
    const int tig  = lane & 3;          // 0..3

    float* const ring = smem + wg * (NBUF * STAGE_F);

    const float* xb = x   + (size_t)b * CIN  * HW;
    float*       ob = out + (size_t)b * COUT * HW;
    const int pwg = blockIdx.x * (2 * NTILE * ITERS) + wg * (NTILE * ITERS);

    // ---- Prefetch tiles 0,1 into ring stages 0,1 ----
#pragma unroll
    for (int t = 0; t < 2; t++) {
#pragma unroll
        for (int j = 0; j < 8; j++) {
            int id  = wtid + 128 * j;     // 0..1023
            int row = id >> 4;            // 0..63
            int q   = id & 15;            // 16B chunk within 64px row
            cp_async16(ring + t * STAGE_F + row * XS + q * 4,
                       xb + row * HW + pwg + t * NTILE + q * 4);
        }
        cp_commit();
    }

    // ---- Stage W (row-major [64][65]) into wg0's stage 2, build afr ----
    float* const wst = smem + 2 * STAGE_F;   // ring(0,2); reclaimed at it=0
    {
        const float* Wg = g_W + b * COUT * CIN;
        for (int idx = tid; idx < COUT * CIN; idx += 256) {
            int o = idx >> 6, i = idx & 63;
            wst[o * 65 + i] = Wg[idx];
        }
    }
    __syncthreads();

    // afr[k][m]: A fragment for m-subtile (rows mi*32 + m*16), k-step k.
    uint32_t afr[8][2][4];
#pragma unroll
    for (int k = 0; k < 8; k++)
#pragma unroll
        for (int m = 0; m < 2; m++) {
            int r0 = mi * 32 + m * 16 + g;
            int kc = k * 8 + tig;
            afr[k][m][0] = __float_as_uint(wst[r0       * 65 + kc]);
            afr[k][m][1] = __float_as_uint(wst[(r0 + 8) * 65 + kc]);
            afr[k][m][2] = __float_as_uint(wst[r0       * 65 + kc + 4]);
            afr[k][m][3] = __float_as_uint(wst[(r0 + 8) * 65 + kc + 4]);
        }
    __syncthreads();   // last CTA-wide sync; wgs independent afterwards

    for (int it = 0; it < ITERS; it++) {
        float* const cur = ring + (it % NBUF) * STAGE_F;
        const int p0 = pwg + it * NTILE;

        if (it < ITERS - 1) cp_wait<1>(); else cp_wait<0>();
        wg_bar(1 + wg);

        // ---- Prefetch tile it+2 ----
        if (it + 2 < ITERS) {
            float* const nxt = ring + ((it + 2) % NBUF) * STAGE_F;
            const int pn = p0 + 2 * NTILE;
#pragma unroll
            for (int j = 0; j < 8; j++) {
                int id  = wtid + 128 * j;
                int row = id >> 4;
                int q   = id & 15;
                cp_async16(nxt + row * XS + q * 4, xb + row * HW + pn + q * 4);
            }
            cp_commit();
        }

        // ---- Compute: 2 m-subtiles x 4 n-subtiles x 8 k-steps ----
        float acc[2][4][4];
#pragma unroll
        for (int m = 0; m < 2; m++)
#pragma unroll
            for (int nt = 0; nt < 4; nt++) {
                acc[m][nt][0] = 0.f; acc[m][nt][1] = 0.f;
                acc[m][nt][2] = 0.f; acc[m][nt][3] = 0.f;
            }
#pragma unroll
        for (int k = 0; k < 8; k++) {
            const float* r0 = cur + (k * 8 + tig)     * XS + ni * 32 + g;
            const float* r1 = cur + (k * 8 + 4 + tig) * XS + ni * 32 + g;
#pragma unroll
            for (int nt = 0; nt < 4; nt++) {
                uint32_t b0 = __float_as_uint(r0[nt * 8]);
                uint32_t b1 = __float_as_uint(r1[nt * 8]);
#pragma unroll
                for (int m = 0; m < 2; m++) {
                    asm volatile(
                        "mma.sync.aligned.m16n8k8.row.col.f32.tf32.tf32.f32 "
                        "{%0,%1,%2,%3}, {%4,%5,%6,%7}, {%8,%9}, {%0,%1,%2,%3};\n"
                        : "+f"(acc[m][nt][0]), "+f"(acc[m][nt][1]),
                          "+f"(acc[m][nt][2]), "+f"(acc[m][nt][3])
                        : "r"(afr[k][m][0]), "r"(afr[k][m][1]),
                          "r"(afr[k][m][2]), "r"(afr[k][m][3]),
                          "r"(b0), "r"(b1));
                }
            }
        }

        // ---- Streaming stores: full 32B sectors ----
#pragma unroll
        for (int m = 0; m < 2; m++) {
            const int r0 = mi * 32 + m * 16 + g;
#pragma unroll
            for (int nt = 0; nt < 4; nt++) {
                const int c = p0 + ni * 32 + nt * 8 + 2 * tig;
                float2 v0 = make_float2(acc[m][nt][0], acc[m][nt][1]);
                float2 v1 = make_float2(acc[m][nt][2], acc[m][nt][3]);
                __stcs(reinterpret_cast<float2*>(ob + (size_t)r0       * HW + c), v0);
                __stcs(reinterpret_cast<float2*>(ob + (size_t)(r0 + 8) * HW + c), v1);
            }
        }
    }
}

extern "C" void kernel_launch(void* const* d_in, const int* in_sizes, int n_in,
                              void* d_out, int out_size) {
    const float* x     = (const float*)d_in[0];   // [32,64,160,160]
    const float* alpha = (const float*)d_in[1];   // [32,8]
    const float* ke    = (const float*)d_in[2];   // [8,64,64,1,1]
    float*       out   = (float*)d_out;           // [32,64,160,160]

    cudaFuncSetAttribute(lla_conv_kernel,
                         cudaFuncAttributeMaxDynamicSharedMemorySize, SMEM_BYTES);

    dim3 wgrid(BATCH, 4);
    lla_weights_kernel<<<wgrid, 256>>>(alpha, ke);

    dim3 grid(HW / (2 * NTILE * ITERS), BATCH);   // (25, 32)
    lla_conv_kernel<<<grid, 256, SMEM_BYTES>>>(x, out);
}